// round 12
// baseline (speedup 1.0000x reference)
#include <cuda_runtime.h>

typedef unsigned long long u64;

#define NB 1024
#define SL 512
#define NL 64

__device__ __forceinline__ u64 fma2(u64 a, u64 b, u64 c) {
    u64 d;
    asm("fma.rn.f32x2 %0, %1, %2, %3;" : "=l"(d) : "l"(a), "l"(b), "l"(c));
    return d;
}
__device__ __forceinline__ u64 add2(u64 a, u64 b) {
    u64 d;
    asm("add.rn.f32x2 %0, %1, %2;" : "=l"(d) : "l"(a), "l"(b));
    return d;
}
__device__ __forceinline__ u64 pack2(float lo, float hi) {
    u64 d;
    asm("mov.b64 %0, {%1, %2};" : "=l"(d) : "f"(lo), "f"(hi));
    return d;
}
__device__ __forceinline__ void unpack2(u64 a, float& lo, float& hi) {
    asm("mov.b64 {%0, %1}, %2;" : "=f"(lo), "=f"(hi) : "l"(a));
}

// MUFU-free exp2 (proven R11): magic round + deg-4 Taylor + exponent splice.
__device__ __forceinline__ float fexp2(float t) {
    const float MAGIC = 12582912.0f;            // 1.5 * 2^23
    const float r  = t + MAGIC;
    const float fn = r - MAGIC;
    const float f  = t - fn;
    float p = 0.0096181f;
    p = fmaf(p, f, 0.0555042f);
    p = fmaf(p, f, 0.2402265f);
    p = fmaf(p, f, 0.6931472f);
    p = fmaf(p, f, 1.0f);
    return __uint_as_float(__float_as_uint(p) + (__float_as_uint(r) << 23));
}

// R11 core (148us) + TWO batches per warp: occupancy is grid-capped at
// ~1.45 warps/SMSP, so ~55% of step time was un-hidden chain latency.
// The E register file (128 regs) is SHARED between the two batches; their
// chains are independent -> ptxas interleaves them (2.9 chains/SMSP).
// Disjoint accumulators per batch (no WAR serialization); ONE __syncwarp
// per time-step covers both double-buffers.
#define STEPB(IB, PB, CBF, EMA, EMB, MK) do {                                 \
    const float cfa = fexp2((EMA) - C2##IB);                                   \
    const float cfb = fexp2((EMB) - C2##IB);                                   \
    const ulonglong2* qp = (const ulonglong2*)qbuf[w][IB][(PB)];               \
    u64 x0 = 0, x1 = 0, y0 = 0, y1 = 0;                                        \
    _Pragma("unroll")                                                          \
    for (int k = 0; k < 8; k++) {                                              \
        ulonglong2 v0 = qp[2 * k];                                             \
        ulonglong2 v1 = qp[2 * k + 1];                                         \
        x0 = fma2(v0.x, Ea[4 * k + 0], x0);  y0 = fma2(v0.x, Eb[4 * k + 0], y0);\
        x1 = fma2(v0.y, Ea[4 * k + 1], x1);  y1 = fma2(v0.y, Eb[4 * k + 1], y1);\
        x0 = fma2(v1.x, Ea[4 * k + 2], x0);  y0 = fma2(v1.x, Eb[4 * k + 2], y0);\
        x1 = fma2(v1.y, Ea[4 * k + 3], x1);  y1 = fma2(v1.y, Eb[4 * k + 3], y1);\
    }                                                                          \
    float xa, ya, xb, yb;                                                      \
    unpack2(add2(x0, x1), xa, ya);                                             \
    unpack2(add2(y0, y1), xb, yb);                                             \
    const float sa = xa + ya;                                                  \
    const float sb = xb + yb;                                                  \
    qa##IB = (MK) ? sa * cfa : qa##IB;                                         \
    qb##IB = (MK) ? sb * cfb : qb##IB;                                         \
    Z2##IB = (MK) ? Z2##IB + C2##IB : Z2##IB;                                  \
    *(float2*)&qbuf[w][IB][(CBF)][ca] = make_float2(qa##IB, qb##IB);           \
} while (0)

#define CUPD(IB, NE) do {                                                     \
    const int n = (int)(__float_as_uint(qa##IB) >> 23) - 127;                  \
    C2##IB = __shfl_sync(FULL, (float)n + (NE), 0);                            \
} while (0)

__global__ __launch_bounds__(64) void crf_fwd_kernel(
    const float* __restrict__ emissions,
    const int*   __restrict__ mask,
    const float* __restrict__ trans,
    const float* __restrict__ startt,
    const float* __restrict__ endt,
    float* __restrict__ out)
{
    __shared__ __align__(16) float qbuf[2][2][2][NL];  // [warp][bat][buf][lbl]

    const int tid = threadIdx.x;
    const int w   = tid >> 5;
    const int l   = tid & 31;
    const int b0  = blockIdx.x * 4 + w * 2;            // this warp: b0, b0+1
    const int ca  = 2 * l;
    const int cb  = 2 * l + 1;
    const unsigned FULL = 0xffffffffu;
    const float LN2 = 0.6931471805599453f;
    const float L2E = 1.4426950408889634f;

    // E columns ca/cb (shared by both batches), adjacent-row-pair packed.
    u64 Ea[32], Eb[32];
#pragma unroll
    for (int m = 0; m < 32; m++) {
        Ea[m] = pack2(__expf(trans[(2 * m) * NL + ca]),
                      __expf(trans[(2 * m + 1) * NL + ca]));
        Eb[m] = pack2(__expf(trans[(2 * m) * NL + cb]),
                      __expf(trans[(2 * m + 1) * NL + cb]));
    }
    const float fend_a = __expf(endt[ca]);
    const float fend_b = __expf(endt[cb]);

    const float* ep0 = emissions + (size_t)b0 * SL * NL + ca;
    const float* ep1 = ep0 + (size_t)SL * NL;
    const int*   mp0 = mask + b0 * SL;
    const int*   mp1 = mp0 + SL;

#define LD2F(P, T) make_float2(L2E * ((const float2*)((P) + (size_t)(T) * NL))->x, \
                               L2E * ((const float2*)((P) + (size_t)(T) * NL))->y)

    // t = 0 init (one-time MUFU is fine)
    float qa0, qb0, Z20, C20, qa1, qb1, Z21, C21;
    {
        float2 e00 = *(const float2*)ep0;
        float2 e01 = *(const float2*)ep1;
        float sa0 = startt[ca] + e00.x, sb0 = startt[cb] + e00.y;
        float sa1 = startt[ca] + e01.x, sb1 = startt[cb] + e01.y;
        float z00 = __shfl_sync(FULL, sa0, 0);
        float z01 = __shfl_sync(FULL, sa1, 0);
        qa0 = __expf(sa0 - z00);  qb0 = __expf(sb0 - z00);  Z20 = z00 * L2E;
        qa1 = __expf(sa1 - z01);  qb1 = __expf(sb1 - z01);  Z21 = z01 * L2E;
        *(float2*)&qbuf[w][0][0][ca] = make_float2(qa0, qb0);
        *(float2*)&qbuf[w][1][0][ca] = make_float2(qa1, qb1);
    }

    // prologue prefetch: t=1..3 + first group t=4..7, both batches
    float2 p01 = LD2F(ep0, 1), p02 = LD2F(ep0, 2), p03 = LD2F(ep0, 3);
    float2 p11 = LD2F(ep1, 1), p12 = LD2F(ep1, 2), p13 = LD2F(ep1, 3);
    float2 g00 = LD2F(ep0, 4), g01 = LD2F(ep0, 5), g02 = LD2F(ep0, 6), g03 = LD2F(ep0, 7);
    float2 g10 = LD2F(ep1, 4), g11 = LD2F(ep1, 5), g12 = LD2F(ep1, 6), g13 = LD2F(ep1, 7);
    const int4 m00 = *(const int4*)mp0;
    const int4 m01 = *(const int4*)mp1;
    int4 mv0 = *(const int4*)(mp0 + 4);
    int4 mv1 = *(const int4*)(mp1 + 4);

    C20 = __shfl_sync(FULL, p01.x, 0);     // q_0 = 1 -> n = 0
    C21 = __shfl_sync(FULL, p11.x, 0);

    // prologue steps t = 1..3
    __syncwarp(FULL);
    STEPB(0, 0, 1, p01.x, p01.y, m00.y);  STEPB(1, 0, 1, p11.x, p11.y, m01.y);
    CUPD(0, p02.x);  CUPD(1, p12.x);
    __syncwarp(FULL);
    STEPB(0, 1, 0, p02.x, p02.y, m00.z);  STEPB(1, 1, 0, p12.x, p12.y, m01.z);
    CUPD(0, p03.x);  CUPD(1, p13.x);
    __syncwarp(FULL);
    STEPB(0, 0, 1, p03.x, p03.y, m00.w);  STEPB(1, 0, 1, p13.x, p13.y, m01.w);
    CUPD(0, g00.x);  CUPD(1, g10.x);

    // main loop: groups of 4, next group prefetched at top (MLP=10)
#pragma unroll 1
    for (int t0 = 4; t0 < SL; t0 += 4) {
        const int tn0 = (t0 + 4 < SL) ? t0 + 4 : SL - 4;   // clamped reload ok
        const float2 n00 = LD2F(ep0, tn0), n01 = LD2F(ep0, tn0 + 1);
        const float2 n02 = LD2F(ep0, tn0 + 2), n03 = LD2F(ep0, tn0 + 3);
        const float2 n10 = LD2F(ep1, tn0), n11 = LD2F(ep1, tn0 + 1);
        const float2 n12 = LD2F(ep1, tn0 + 2), n13 = LD2F(ep1, tn0 + 3);
        const int4 nmv0 = *(const int4*)(mp0 + tn0);
        const int4 nmv1 = *(const int4*)(mp1 + tn0);

        __syncwarp(FULL);
        STEPB(0, 1, 0, g00.x, g00.y, mv0.x);  STEPB(1, 1, 0, g10.x, g10.y, mv1.x);
        CUPD(0, g01.x);  CUPD(1, g11.x);
        __syncwarp(FULL);
        STEPB(0, 0, 1, g01.x, g01.y, mv0.y);  STEPB(1, 0, 1, g11.x, g11.y, mv1.y);
        CUPD(0, g02.x);  CUPD(1, g12.x);
        __syncwarp(FULL);
        STEPB(0, 1, 0, g02.x, g02.y, mv0.z);  STEPB(1, 1, 0, g12.x, g12.y, mv1.z);
        CUPD(0, g03.x);  CUPD(1, g13.x);
        __syncwarp(FULL);
        STEPB(0, 0, 1, g03.x, g03.y, mv0.w);  STEPB(1, 0, 1, g13.x, g13.y, mv1.w);
        CUPD(0, n00.x);  CUPD(1, n10.x);

        g00 = n00; g01 = n01; g02 = n02; g03 = n03;
        g10 = n10; g11 = n11; g12 = n12; g13 = n13;
        mv0 = nmv0; mv1 = nmv1;
    }

    // outputs
    float v0 = qa0 * fend_a + qb0 * fend_b;
    float v1 = qa1 * fend_a + qb1 * fend_b;
#pragma unroll
    for (int o = 16; o; o >>= 1) {
        v0 += __shfl_xor_sync(FULL, v0, o);
        v1 += __shfl_xor_sync(FULL, v1, o);
    }
    if (l == 0) {
        out[b0]     = fmaf(Z20, LN2, __logf(v0));
        out[b0 + 1] = fmaf(Z21, LN2, __logf(v1));
    }
#undef LD2F
}

extern "C" void kernel_launch(void* const* d_in, const int* in_sizes, int n_in,
                              void* d_out, int out_size) {
    const float* emissions = (const float*)d_in[0];
    const int*   msk       = (const int*)d_in[1];
    const float* trans     = (const float*)d_in[2];
    const float* startt    = (const float*)d_in[3];
    const float* endt      = (const float*)d_in[4];
    crf_fwd_kernel<<<NB / 4, 64>>>(emissions, msk, trans, startt, endt, (float*)d_out);
}

// round 13
// speedup vs baseline: 1.5886x; 1.5886x over previous
#include <cuda_runtime.h>

typedef unsigned long long u64;

#define NB 1024
#define SL 512
#define NL 64

__device__ __forceinline__ u64 fma2(u64 a, u64 b, u64 c) {
    u64 d;
    asm("fma.rn.f32x2 %0, %1, %2, %3;" : "=l"(d) : "l"(a), "l"(b), "l"(c));
    return d;
}
__device__ __forceinline__ u64 add2(u64 a, u64 b) {
    u64 d;
    asm("add.rn.f32x2 %0, %1, %2;" : "=l"(d) : "l"(a), "l"(b));
    return d;
}
__device__ __forceinline__ u64 pack2(float lo, float hi) {
    u64 d;
    asm("mov.b64 %0, {%1, %2};" : "=l"(d) : "f"(lo), "f"(hi));
    return d;
}
__device__ __forceinline__ void unpack2(u64 a, float& lo, float& hi) {
    asm("mov.b64 {%0, %1}, %2;" : "=f"(lo), "=f"(hi) : "l"(a));
}

// MUFU-free exp2 (proven R11): magic round + deg-4 Taylor + exponent splice.
__device__ __forceinline__ float fexp2(float t) {
    const float MAGIC = 12582912.0f;            // 1.5 * 2^23
    const float r  = t + MAGIC;
    const float fn = r - MAGIC;
    const float f  = t - fn;
    float p = 0.0096181f;
    p = fmaf(p, f, 0.0555042f);
    p = fmaf(p, f, 0.2402265f);
    p = fmaf(p, f, 0.6931472f);
    p = fmaf(p, f, 1.0f);
    return __uint_as_float(__float_as_uint(p) + (__float_as_uint(r) << 23));
}

// R1 layout (64-thread block = 1 batch, thread j owns column j, ONE
// __syncthreads per step, 2048 warps -> 3.46 warps/SMSP of latency hiding)
// combined with R11's proven math:
//  - log2-domain multiplicative recurrence (exact for any scalar C2):
//      s_j = sum_i q_i E_ij ; q'_j = s_j * exp2(e2_j - C2) ; Z2 += C2
//  - fexp2 on fma/alu pipes (NO MUFU in the hot loop)
//  - C2 re-anchored every step from exponent(q_0) (uniform ALU; only the
//    4B STS is guarded), published via smem scalar
//  - time-unroll x4 with group-ahead emission prefetch (MLP=5) — R1's 790
//    cyc/step was exactly the MLP=1 DRAM latency; this removes it.
#define STEP(PB, CBF, E2, MK, E2N) do {                                       \
    __syncthreads();                                                           \
    const float C2 = csm[(PB)];                                                \
    const float cf = fexp2((E2) - C2);                                         \
    const ulonglong2* qp = (const ulonglong2*)qbuf[(PB)];                      \
    u64 a0 = 0, a1 = 0, a2 = 0, a3 = 0;                                        \
    _Pragma("unroll")                                                          \
    for (int k = 0; k < 8; k++) {                                              \
        ulonglong2 v0 = qp[2 * k];                                             \
        ulonglong2 v1 = qp[2 * k + 1];                                         \
        a0 = fma2(v0.x, E[4 * k + 0], a0);                                     \
        a1 = fma2(v0.y, E[4 * k + 1], a1);                                     \
        a2 = fma2(v1.x, E[4 * k + 2], a2);                                     \
        a3 = fma2(v1.y, E[4 * k + 3], a3);                                     \
    }                                                                          \
    float sx, sy;                                                              \
    unpack2(add2(add2(a0, a1), add2(a2, a3)), sx, sy);                         \
    const float s = sx + sy;                                                   \
    q  = (MK) ? s * cf  : q;                                                   \
    Z2 = (MK) ? Z2 + C2 : Z2;                                                  \
    qbuf[(CBF)][j] = q;                                                        \
    const int nn = (int)(__float_as_uint(q) >> 23) - 127;                      \
    const float Cn = (float)nn + (E2N);                                        \
    if (tid == 0) csm[(CBF)] = Cn;                                             \
} while (0)

__global__ __launch_bounds__(64) void crf_fwd_kernel(
    const float* __restrict__ emissions,
    const int*   __restrict__ mask,
    const float* __restrict__ trans,
    const float* __restrict__ startt,
    const float* __restrict__ endt,
    float* __restrict__ out)
{
    __shared__ __align__(16) float qbuf[2][NL];
    __shared__ float csm[2];
    __shared__ float red[2];

    const int tid = threadIdx.x;
    const int w   = tid >> 5;
    const int l   = tid & 31;
    const int b   = blockIdx.x;
    const int j   = tid;                       // owned column
    const float* ep = emissions + (size_t)b * SL * NL + j;   // ep[t*NL]
    const int*   mp = mask + b * SL;
    const unsigned FULL = 0xffffffffu;
    const float LN2 = 0.6931471805599453f;
    const float L2E = 1.4426950408889634f;

    // E column j, packed over adjacent row pairs (matches q smem layout).
    u64 E[32];
#pragma unroll
    for (int m = 0; m < 32; m++) {
        E[m] = pack2(__expf(trans[(2 * m) * NL + j]),
                     __expf(trans[(2 * m + 1) * NL + j]));
    }
    const float fend = __expf(endt[j]);

    // t = 0: normalize by score_0 -> q_0 = 1 exactly (one-time MUFU ok).
    const float sc = startt[j] + ep[0];
    if (tid == 0) red[0] = sc;
    __syncthreads();
    const float z0 = red[0];
    float q  = __expf(sc - z0);
    float Z2 = z0 * L2E;                        // log2-domain accumulator
    qbuf[0][j] = q;

    // prefetch t = 1..7 (log2-scaled) + masks, MLP ~ 9
    float e1 = L2E * ep[(size_t)1 * NL];
    float e2 = L2E * ep[(size_t)2 * NL];
    float e3 = L2E * ep[(size_t)3 * NL];
    float g0 = L2E * ep[(size_t)4 * NL];
    float g1 = L2E * ep[(size_t)5 * NL];
    float g2 = L2E * ep[(size_t)6 * NL];
    float g3 = L2E * ep[(size_t)7 * NL];
    const int4 m0 = *(const int4*)mp;           // .y,.z,.w -> t = 1,2,3
    int4 mv = *(const int4*)(mp + 4);           // t = 4..7

    if (tid == 0) csm[0] = e1;                  // C2_1 = e2_0^1 (q_0 = 1)

    // prologue: t = 1..3
    STEP(0, 1, e1, m0.y, e2);
    STEP(1, 0, e2, m0.z, e3);
    STEP(0, 1, e3, m0.w, g0);

    // main loop: groups of 4, next group prefetched at group top (MLP = 5)
#pragma unroll 1
    for (int t0 = 4; t0 < SL; t0 += 4) {
        const int tn0 = (t0 + 4 < SL) ? t0 + 4 : SL - 4;    // clamped reload ok
        const float n0 = L2E * ep[(size_t)(tn0    ) * NL];
        const float n1 = L2E * ep[(size_t)(tn0 + 1) * NL];
        const float n2 = L2E * ep[(size_t)(tn0 + 2) * NL];
        const float n3 = L2E * ep[(size_t)(tn0 + 3) * NL];
        const int4 nmv = *(const int4*)(mp + tn0);

        STEP(1, 0, g0, mv.x, g1);
        STEP(0, 1, g1, mv.y, g2);
        STEP(1, 0, g2, mv.z, g3);
        STEP(0, 1, g3, mv.w, n0);

        g0 = n0; g1 = n1; g2 = n2; g3 = n3; mv = nmv;
    }

    // out[b] = Z2*ln2 + ln( sum_j q_j * exp(end_j) )
    float v = q * fend;
#pragma unroll
    for (int o = 16; o; o >>= 1) v += __shfl_xor_sync(FULL, v, o);
    if (l == 0) red[w] = v;
    __syncthreads();
    if (tid == 0) out[b] = fmaf(Z2, LN2, __logf(red[0] + red[1]));
}

extern "C" void kernel_launch(void* const* d_in, const int* in_sizes, int n_in,
                              void* d_out, int out_size) {
    const float* emissions = (const float*)d_in[0];
    const int*   msk       = (const int*)d_in[1];
    const float* trans     = (const float*)d_in[2];
    const float* startt    = (const float*)d_in[3];
    const float* endt      = (const float*)d_in[4];
    crf_fwd_kernel<<<NB, NL>>>(emissions, msk, trans, startt, endt, (float*)d_out);
}

// round 14
// speedup vs baseline: 1.8216x; 1.1466x over previous
#include <cuda_runtime.h>

typedef unsigned long long u64;

#define NB 1024
#define SL 512
#define NL 64

__device__ __forceinline__ u64 fma2(u64 a, u64 b, u64 c) {
    u64 d;
    asm("fma.rn.f32x2 %0, %1, %2, %3;" : "=l"(d) : "l"(a), "l"(b), "l"(c));
    return d;
}
__device__ __forceinline__ u64 add2(u64 a, u64 b) {
    u64 d;
    asm("add.rn.f32x2 %0, %1, %2;" : "=l"(d) : "l"(a), "l"(b));
    return d;
}
__device__ __forceinline__ u64 pack2(float lo, float hi) {
    u64 d;
    asm("mov.b64 %0, {%1, %2};" : "=l"(d) : "f"(lo), "f"(hi));
    return d;
}
__device__ __forceinline__ void unpack2(u64 a, float& lo, float& hi) {
    asm("mov.b64 {%0, %1}, %2;" : "=f"(lo), "=f"(hi) : "l"(a));
}

// MUFU-free exp2 (proven R11): magic round + deg-4 Taylor + exponent splice.
__device__ __forceinline__ float fexp2(float t) {
    const float MAGIC = 12582912.0f;            // 1.5 * 2^23
    const float r  = t + MAGIC;
    const float fn = r - MAGIC;
    const float f  = t - fn;
    float p = 0.0096181f;
    p = fmaf(p, f, 0.0555042f);
    p = fmaf(p, f, 0.2402265f);
    p = fmaf(p, f, 0.6931472f);
    p = fmaf(p, f, 1.0f);
    return __uint_as_float(__float_as_uint(p) + (__float_as_uint(r) << 23));
}

// R11 champion (148us) repacked into 128-thread CTAs = 4 INDEPENDENT warps =
// 4 batches. SMSP = wid%4: R11's 64-thread CTAs put all warps on SMSP 0/1
// only (active-SMSP issue ~77% = saturated); 4-warp CTAs engage all four
// schedulers at identical total warp count. Per-warp code is R11 verbatim:
// lane l owns columns (2l, 2l+1); 16 LDS.128 + 64 fma2 per step; log2-domain
// multiplicative recurrence; fexp2 (no hot-loop MUFU); per-step re-anchored
// scalar normalizer; time-unroll x4 with group prefetch (MLP=5); selects.
#define STEP(PB, CBF, EMA, EMB, MK) do {                                      \
    __syncwarp(FULL);                                                          \
    const float cfa = fexp2((EMA) - C2);                                       \
    const float cfb = fexp2((EMB) - C2);                                       \
    const ulonglong2* qp = (const ulonglong2*)qbuf[w][(PB)];                   \
    u64 a0 = 0, a1 = 0, c0 = 0, c1 = 0;                                        \
    _Pragma("unroll")                                                          \
    for (int k = 0; k < 8; k++) {                                              \
        ulonglong2 v0 = qp[2 * k];                                             \
        ulonglong2 v1 = qp[2 * k + 1];                                         \
        a0 = fma2(v0.x, Ea[4 * k + 0], a0);  c0 = fma2(v0.x, Eb[4 * k + 0], c0);\
        a1 = fma2(v0.y, Ea[4 * k + 1], a1);  c1 = fma2(v0.y, Eb[4 * k + 1], c1);\
        a0 = fma2(v1.x, Ea[4 * k + 2], a0);  c0 = fma2(v1.x, Eb[4 * k + 2], c0);\
        a1 = fma2(v1.y, Ea[4 * k + 3], a1);  c1 = fma2(v1.y, Eb[4 * k + 3], c1);\
    }                                                                          \
    float xa, ya, xb, yb;                                                      \
    unpack2(add2(a0, a1), xa, ya);                                             \
    unpack2(add2(c0, c1), xb, yb);                                             \
    const float sa = xa + ya;                                                  \
    const float sb = xb + yb;                                                  \
    qa = (MK) ? sa * cfa : qa;                                                 \
    qb = (MK) ? sb * cfb : qb;                                                 \
    Z2 = (MK) ? Z2 + C2  : Z2;                                                 \
    *(float2*)&qbuf[w][(CBF)][ca] = make_float2(qa, qb);                       \
} while (0)

#define CUPD(NEXT_E2) do {                                                    \
    const int n = (int)(__float_as_uint(qa) >> 23) - 127;                      \
    C2 = __shfl_sync(FULL, (float)n + (NEXT_E2), 0);                           \
} while (0)

__global__ __launch_bounds__(128) void crf_fwd_kernel(
    const float* __restrict__ emissions,
    const int*   __restrict__ mask,
    const float* __restrict__ trans,
    const float* __restrict__ startt,
    const float* __restrict__ endt,
    float* __restrict__ out)
{
    __shared__ __align__(16) float qbuf[4][2][NL];   // [warp][buf][label]

    const int tid = threadIdx.x;
    const int w   = tid >> 5;
    const int l   = tid & 31;
    const int b   = blockIdx.x * 4 + w;
    const size_t ebase = (size_t)b * SL * NL;
    const int ca = 2 * l;
    const int cb = 2 * l + 1;
    const unsigned FULL = 0xffffffffu;
    const float LN2 = 0.6931471805599453f;
    const float L2E = 1.4426950408889634f;

    // E columns ca/cb, packed over adjacent row pairs (rows 2m, 2m+1).
    u64 Ea[32], Eb[32];
#pragma unroll
    for (int m = 0; m < 32; m++) {
        Ea[m] = pack2(__expf(trans[(2 * m) * NL + ca]),
                      __expf(trans[(2 * m + 1) * NL + ca]));
        Eb[m] = pack2(__expf(trans[(2 * m) * NL + cb]),
                      __expf(trans[(2 * m + 1) * NL + cb]));
    }
    const float fend_a = __expf(endt[ca]);
    const float fend_b = __expf(endt[cb]);

#define LD2(T) make_float2(L2E * (*(const float2*)&emissions[ebase + (size_t)(T) * NL + ca]).x, \
                           L2E * (*(const float2*)&emissions[ebase + (size_t)(T) * NL + ca]).y)

    // upfront prefetch: t=0..7 emissions (log2-scaled) + masks
    float2 e0  = *(const float2*)&emissions[ebase + (size_t)0 * NL + ca];
    float2 em1 = LD2(1);
    float2 em2 = LD2(2);
    float2 em3 = LD2(3);
    float2 eb0 = LD2(4);
    float2 eb1 = LD2(5);
    float2 eb2 = LD2(6);
    float2 eb3 = LD2(7);
    const int4 m0 = *(const int4*)&mask[b * SL];      // .y,.z,.w -> t=1,2,3
    int4 mv = *(const int4*)&mask[b * SL + 4];        // t=4..7

    // t = 0: normalize by score of label 0 -> q_0 = 1 exactly.
    float sc_a = startt[ca] + e0.x;
    float sc_b = startt[cb] + e0.y;
    const float z0 = __shfl_sync(FULL, sc_a, 0);
    float qa = __expf(sc_a - z0);
    float qb = __expf(sc_b - z0);
    float Z2 = z0 * L2E;                       // log2-domain accumulator
    *(float2*)&qbuf[w][0][ca] = make_float2(qa, qb);

    float C2 = __shfl_sync(FULL, em1.x, 0);    // C2_1 = e2_0^1 (q_0 = 1)

    // prologue: t = 1..3
    STEP(0, 1, em1.x, em1.y, m0.y);  CUPD(em2.x);
    STEP(1, 0, em2.x, em2.y, m0.z);  CUPD(em3.x);
    STEP(0, 1, em3.x, em3.y, m0.w);  CUPD(eb0.x);

    // main loop: groups of 4, next group prefetched at group top (MLP=5)
#pragma unroll 1
    for (int t0 = 4; t0 < SL; t0 += 4) {
        const int tn0 = (t0 + 4 < SL) ? t0 + 4 : SL - 4;   // clamped reload;
        const float2 nb0 = LD2(tn0);                        // any scalar C2 is
        const float2 nb1 = LD2(tn0 + 1);                    // algebraically exact
        const float2 nb2 = LD2(tn0 + 2);
        const float2 nb3 = LD2(tn0 + 3);
        const int4   nmv = *(const int4*)&mask[b * SL + tn0];

        STEP(1, 0, eb0.x, eb0.y, mv.x);  CUPD(eb1.x);
        STEP(0, 1, eb1.x, eb1.y, mv.y);  CUPD(eb2.x);
        STEP(1, 0, eb2.x, eb2.y, mv.z);  CUPD(eb3.x);
        STEP(0, 1, eb3.x, eb3.y, mv.w);  CUPD(nb0.x);

        eb0 = nb0; eb1 = nb1; eb2 = nb2; eb3 = nb3; mv = nmv;
    }

    // out[b] = Z2*ln2 + ln( sum_j q_j * exp(end_j) )
    float v = qa * fend_a + qb * fend_b;
#pragma unroll
    for (int o = 16; o; o >>= 1) v += __shfl_xor_sync(FULL, v, o);
    if (l == 0) out[b] = fmaf(Z2, LN2, __logf(v));
#undef LD2
}

extern "C" void kernel_launch(void* const* d_in, const int* in_sizes, int n_in,
                              void* d_out, int out_size) {
    const float* emissions = (const float*)d_in[0];
    const int*   msk       = (const int*)d_in[1];
    const float* trans     = (const float*)d_in[2];
    const float* startt    = (const float*)d_in[3];
    const float* endt      = (const float*)d_in[4];
    crf_fwd_kernel<<<NB / 4, 128>>>(emissions, msk, trans, startt, endt, (float*)d_out);
}